// round 14
// baseline (speedup 1.0000x reference)
#include <cuda_runtime.h>
#include <cuda_fp16.h>
#include <cstdint>

#define BB 2
#define SS 2048
#define DD 1024
#define HH 16
#define HDD 64
#define BHH 32
#define MTOT 4096
#define NQKV 3072

// operands (__device__ globals: allocation-free rule), 16B aligned
__device__ __align__(16) __half g_xh[MTOT*DD];                     // x [m][k]
__device__ __align__(16) __half g_wqh[DD*NQKV];                    // W_qkv [k][n]
__device__ __align__(16) __half g_woh[DD*DD];                      // W_out  [k][n]
__device__ __align__(16) __half g_qh[BHH*SS*HDD];                  // q (pre-scaled by 0.125*log2e)
__device__ __align__(16) __half g_kh[BHH*SS*HDD];                  // k
__device__ __align__(16) __half g_vh[BHH*SS*HDD];                  // v
__device__ __align__(16) __half g_ao[MTOT*DD];                     // attn out [b*s][d]

// ---------------- helpers ----------------
__device__ __forceinline__ uint32_t smem_u32(const void* p){
    uint32_t a;
    asm("{ .reg .u64 t; cvta.to.shared.u64 t, %1; cvt.u32.u64 %0, t; }":"=r"(a):"l"(p));
    return a;
}
__device__ __forceinline__ void cp16(uint32_t d, const void* s){
    asm volatile("cp.async.cg.shared.global [%0], [%1], 16;"::"r"(d),"l"(s));
}
__device__ __forceinline__ void cp_commit(){ asm volatile("cp.async.commit_group;":::"memory"); }
template<int N> __device__ __forceinline__ void cp_wait(){
    asm volatile("cp.async.wait_group %0;"::"n"(N):"memory");
}
__device__ __forceinline__ void ldsm4(uint32_t* r, uint32_t a){
    asm volatile("ldmatrix.sync.aligned.m8n8.x4.shared.b16 {%0,%1,%2,%3}, [%4];"
        :"=r"(r[0]),"=r"(r[1]),"=r"(r[2]),"=r"(r[3]):"r"(a));
}
__device__ __forceinline__ void ldsm4t(uint32_t* r, uint32_t a){
    asm volatile("ldmatrix.sync.aligned.m8n8.x4.trans.shared.b16 {%0,%1,%2,%3}, [%4];"
        :"=r"(r[0]),"=r"(r[1]),"=r"(r[2]),"=r"(r[3]):"r"(a));
}
__device__ __forceinline__ void mma_h(float* c, const uint32_t* a, uint32_t b0, uint32_t b1){
    asm volatile("mma.sync.aligned.m16n8k16.row.col.f32.f16.f16.f32 "
        "{%0,%1,%2,%3}, {%4,%5,%6,%7}, {%8,%9}, {%0,%1,%2,%3};"
        :"+f"(c[0]),"+f"(c[1]),"+f"(c[2]),"+f"(c[3])
        :"r"(a[0]),"r"(a[1]),"r"(a[2]),"r"(a[3]),"r"(b0),"r"(b1));
}
__device__ __forceinline__ uint32_t packh(float x, float y){
    __half2 t = __floats2half2_rn(x, y);
    return *reinterpret_cast<uint32_t*>(&t);
}
__device__ __forceinline__ float ex2(float x){
    float y; asm("ex2.approx.f32 %0, %1;":"=f"(y):"f"(x)); return y;
}

#define QSCL 0.18033688f   // 0.125 * log2(e), folded into q

// ---------------- prep: fp32 -> fp16 ----------------
template<int SEL>
__global__ __launch_bounds__(256)
void conv_h(const float* __restrict__ src, int n4){
    __half* dst = (SEL==0)? g_xh : (SEL==1)? g_wqh : g_woh;
    int i = blockIdx.x*256 + threadIdx.x;
    if (i >= n4) return;
    float4 v = reinterpret_cast<const float4*>(src)[i];
    reinterpret_cast<uint32_t*>(dst)[i*2+0] = packh(v.x, v.y);
    reinterpret_cast<uint32_t*>(dst)[i*2+1] = packh(v.z, v.w);
}

// ---------------- fp16 GEMM: 128x128 CTA tile, 4 warps of 64x64, k-chunk 64 ----
// A tile: 128 rows x 64 fp16 (128B data, 144B stride) -> 18432 B
// B tile:  64 k    x 128 fp16 (256B data, 272B stride) -> 17408 B
#define GSTAGE 35840
#define GSMEM  (3*GSTAGE)

template<int MODE>
__global__ __launch_bounds__(128, 2)
void gemm_mma(const float* __restrict__ bias, float* __restrict__ Cout){
    extern __shared__ char smem[];
    const __half* __restrict__ Ah = (MODE==0)? g_xh  : g_ao;
    const __half* __restrict__ Bh = (MODE==0)? g_wqh : g_woh;
    const int N = (MODE==0)? NQKV : DD;

    const int bm = blockIdx.y*128, bn = blockIdx.x*128;
    const int tid = threadIdx.x, lane = tid&31, wid = tid>>5;
    const int wm = wid>>1, wn = wid&1;   // warp tile 64(M) x 64(N)
    uint32_t sb = smem_u32(smem);

    float acc[4][8][4];
    #pragma unroll
    for (int a=0;a<4;a++)
        #pragma unroll
        for (int b=0;b<8;b++)
            #pragma unroll
            for (int c=0;c<4;c++) acc[a][b][c]=0.f;

    auto load_stage = [&](int t, int s){
        uint32_t as  = sb + s*GSTAGE;
        uint32_t bs2 = as + 18432;
        int k0 = t*64;
        // A: 128 rows x 8 segs = 1024 x 16B
        #pragma unroll
        for (int i=0;i<8;i++){
            int id = i*128 + tid;
            int row = id>>3, seg = id&7;
            cp16(as + row*144 + seg*16, Ah + (size_t)(bm+row)*DD + k0 + seg*8);
        }
        // B: 64 rows x 16 segs = 1024 x 16B
        #pragma unroll
        for (int i=0;i<8;i++){
            int id = i*128 + tid;
            int row = id>>4, seg = id&15;
            cp16(bs2 + row*272 + seg*16, Bh + (size_t)(k0+row)*N + bn + seg*8);
        }
        cp_commit();
    };

    load_stage(0,0);
    load_stage(1,1);
    int sl = 0, sl2 = 2;
    for (int t=0; t<16; t++){
        if (t<15) cp_wait<1>(); else cp_wait<0>();
        __syncthreads();
        if (t+2 < 16) load_stage(t+2, sl2);

        uint32_t as  = sb + sl*GSTAGE;
        uint32_t bs2 = as + 18432;
        #pragma unroll
        for (int k16=0;k16<4;k16++){
            uint32_t ah[4][4];
            #pragma unroll
            for (int mf=0;mf<4;mf++){
                uint32_t ad = as + (uint32_t)(wm*64+mf*16+(lane&15))*144
                            + k16*32 + ((lane>>4)<<4);
                ldsm4(ah[mf], ad);
            }
            uint32_t bhf[8][2];
            #pragma unroll
            for (int g=0;g<4;g++){
                uint32_t kk = (uint32_t)(k16*16 + (lane&15));
                uint32_t bd = bs2 + kk*272
                            + ((uint32_t)(wn*64 + g*16 + ((lane>>4)<<3))<<1);
                uint32_t t4[4];
                ldsm4t(t4, bd);
                bhf[g*2][0]=t4[0]; bhf[g*2][1]=t4[1];
                bhf[g*2+1][0]=t4[2]; bhf[g*2+1][1]=t4[3];
            }
            #pragma unroll
            for (int mf=0;mf<4;mf++)
                #pragma unroll
                for (int nf=0;nf<8;nf++)
                    mma_h(acc[mf][nf], ah[mf], bhf[nf][0], bhf[nf][1]);
        }
        sl  = (sl ==2)? 0 : sl+1;
        sl2 = (sl2==2)? 0 : sl2+1;
    }

    // epilogue
    #pragma unroll
    for (int mf=0;mf<4;mf++){
        #pragma unroll
        for (int nf=0;nf<8;nf++){
            int n0 = bn + wn*64 + nf*8 + ((lane&3)<<1);
            float b0v = bias[n0], b1v = bias[n0+1];
            #pragma unroll
            for (int hf2=0; hf2<2; hf2++){
                int m = bm + wm*64 + mf*16 + (lane>>2) + hf2*8;
                float v0 = acc[mf][nf][hf2*2+0] + b0v;
                float v1 = acc[mf][nf][hf2*2+1] + b1v;
                if (MODE==0){
                    int b = m>>11, s = m&(SS-1);
                    int h = n0/192, r = n0 - h*192;
                    size_t base = ((size_t)(b*HH+h)*SS + s)*HDD;
                    if (r < 64)       *(uint32_t*)(g_qh+base+r)     = packh(v0*QSCL,v1*QSCL);
                    else if (r < 128) *(uint32_t*)(g_kh+base+r-64)  = packh(v0,v1);
                    else              *(uint32_t*)(g_vh+base+r-128) = packh(v0,v1);
                } else {
                    float2 ov; ov.x = v0; ov.y = v1;
                    *(float2*)(Cout + (size_t)m*DD + n0) = ov;
                }
            }
        }
    }
}

// ---------------- flash attention, single fp16 operands ----------------
// CTA: 128 q-rows, 8 warps (warp = 16 rows x 64 cols). k-tiles 64, K/V dbl-buffered.
// Q pre-scaled by QSCL, so S-MMA output is already in log2 domain.
#define QTILE 18432
#define KTILE 9216
#define ASMEM (QTILE + 4*KTILE)   // 55296

__global__ __launch_bounds__(256, 2)
void attn_mma(){
    extern __shared__ char smem[];
    const int bh = blockIdx.y;
    const int qt = (int)gridDim.x - 1 - (int)blockIdx.x;   // big tiles first
    const int qs = qt*128;
    const int tid = threadIdx.x, lane = tid&31, wid = tid>>5;
    uint32_t sb = smem_u32(smem);
    const uint32_t Qs = sb;
    const uint32_t Kb[2] = {sb + QTILE, sb + QTILE + KTILE};
    const uint32_t Vb[2] = {sb + QTILE + 2*KTILE, sb + QTILE + 3*KTILE};
    const size_t hb = (size_t)bh*SS*HDD;
    const __half *qh = g_qh+hb, *kh = g_kh+hb, *vh = g_vh+hb;

    // Q tile: 1024 x 16B
    #pragma unroll
    for (int i=0;i<4;i++){
        int id = i*256+tid, row = id>>3, seg = id&7;
        cp16(Qs + row*144 + seg*16, qh + (size_t)(qs+row)*HDD + seg*8);
    }
    cp_commit();

    auto load_kv = [&](int jt, int b){
        int ks = jt*64;
        #pragma unroll
        for (int i=0;i<2;i++){
            int id = i*256+tid, row = id>>3, seg = id&7;
            cp16(Kb[b] + row*144 + seg*16, kh + (size_t)(ks+row)*HDD + seg*8);
        }
        #pragma unroll
        for (int i=0;i<2;i++){
            int id = i*256+tid, row = id>>3, seg = id&7;
            cp16(Vb[b] + row*144 + seg*16, vh + (size_t)(ks+row)*HDD + seg*8);
        }
        cp_commit();
    };
    load_kv(0, 0);

    float o[8][4];
    #pragma unroll
    for (int a=0;a<8;a++)
        #pragma unroll
        for (int b=0;b<4;b++) o[a][b]=0.f;
    float m0 = -1e30f, m1 = -1e30f, l0 = 0.f, l1 = 0.f;  // l: per-thread partial
    const int rg0 = qs + wid*16 + (lane>>2);
    const int rg1 = rg0 + 8;
    const int njt = 2*qt + 2;

    auto tile_step = [&](int jt, bool dia){
        cp_wait<0>();
        __syncthreads();
        if (jt+1 < njt) load_kv(jt+1, (jt+1)&1);

        const int ks = jt*64;
        const uint32_t Kc = Kb[jt&1], Vc = Vb[jt&1];

        // S = Q K^T (already log2-scaled via Q)
        float s[8][4];
        #pragma unroll
        for (int a=0;a<8;a++)
            #pragma unroll
            for (int b=0;b<4;b++) s[a][b]=0.f;
        #pragma unroll
        for (int kc=0; kc<4; kc++){
            uint32_t qf[4];
            uint32_t qa = Qs + (uint32_t)(wid*16 + (lane&15))*144
                        + kc*32 + ((lane>>4)<<4);
            ldsm4(qf, qa);
            uint32_t kt[4][4];
            #pragma unroll
            for (int np=0; np<4; np++){
                uint32_t row = (uint32_t)(np*16 + ((lane>>4)<<3) + (lane&7));
                uint32_t ka = Kc + row*144 + kc*32 + (((lane>>3)&1)<<4);
                ldsm4(kt[np], ka);
            }
            #pragma unroll
            for (int np=0; np<4; np++){
                mma_h(s[np*2],   qf, kt[np][0], kt[np][1]);
                mma_h(s[np*2+1], qf, kt[np][2], kt[np][3]);
            }
        }
        if (dia){
            #pragma unroll
            for (int nf=0; nf<8; nf++){
                int c = ks + nf*8 + ((lane&3)<<1);
                if (c   > rg0) s[nf][0] = -1e30f;
                if (c+1 > rg0) s[nf][1] = -1e30f;
                if (c   > rg1) s[nf][2] = -1e30f;
                if (c+1 > rg1) s[nf][3] = -1e30f;
            }
        }
        // row maxima (quad reduction; needed for uniform alpha)
        float mx0 = -1e30f, mx1 = -1e30f;
        #pragma unroll
        for (int nf=0;nf<8;nf++){
            mx0 = fmaxf(mx0, fmaxf(s[nf][0], s[nf][1]));
            mx1 = fmaxf(mx1, fmaxf(s[nf][2], s[nf][3]));
        }
        mx0 = fmaxf(mx0, __shfl_xor_sync(0xffffffffu, mx0, 1));
        mx0 = fmaxf(mx0, __shfl_xor_sync(0xffffffffu, mx0, 2));
        mx1 = fmaxf(mx1, __shfl_xor_sync(0xffffffffu, mx1, 1));
        mx1 = fmaxf(mx1, __shfl_xor_sync(0xffffffffu, mx1, 2));
        float m0n = fmaxf(m0, mx0), m1n = fmaxf(m1, mx1);
        float a0 = ex2(m0 - m0n), a1 = ex2(m1 - m1n);
        m0 = m0n; m1 = m1n;

        // P = 2^(S - m); l kept as per-thread partial (alpha is quad-uniform)
        float sum0 = 0.f, sum1 = 0.f;
        uint32_t ph[4][4];
        #pragma unroll
        for (int kc=0; kc<4; kc++){
            #pragma unroll
            for (int half=0; half<2; half++){
                int nf = kc*2 + half;
                float p0 = ex2(s[nf][0]-m0n), p1 = ex2(s[nf][1]-m0n);
                float p2 = ex2(s[nf][2]-m1n), p3 = ex2(s[nf][3]-m1n);
                sum0 += p0+p1; sum1 += p2+p3;
                ph[kc][half*2+0] = packh(p0,p1);
                ph[kc][half*2+1] = packh(p2,p3);
            }
        }
        l0 = l0*a0 + sum0; l1 = l1*a1 + sum1;
        #pragma unroll
        for (int nf=0;nf<8;nf++){
            o[nf][0]*=a0; o[nf][1]*=a0; o[nf][2]*=a1; o[nf][3]*=a1;
        }

        // O += P @ V
        #pragma unroll
        for (int kc=0; kc<4; kc++){
            uint32_t vf[4][4];
            #pragma unroll
            for (int g=0; g<4; g++){
                uint32_t va = Vc + (uint32_t)(kc*16 + (lane&15))*144
                            + ((uint32_t)(g*16 + ((lane>>4)<<3))<<1);
                ldsm4t(vf[g], va);
            }
            #pragma unroll
            for (int g=0; g<4; g++){
                mma_h(o[g*2],   ph[kc], vf[g][0], vf[g][1]);
                mma_h(o[g*2+1], ph[kc], vf[g][2], vf[g][3]);
            }
        }
    };

    for (int jt=0; jt<njt-2; jt++) tile_step(jt, false);
    tile_step(njt-2, true);
    tile_step(njt-1, true);

    // epilogue: quad-reduce l, then o/l -> fp16 -> g_ao[b*s][h*64+d]
    l0 += __shfl_xor_sync(0xffffffffu, l0, 1);
    l0 += __shfl_xor_sync(0xffffffffu, l0, 2);
    l1 += __shfl_xor_sync(0xffffffffu, l1, 1);
    l1 += __shfl_xor_sync(0xffffffffu, l1, 2);
    const int b = bh >> 4, h = bh & 15;
    float inv0 = 1.0f/l0, inv1 = 1.0f/l1;
    int r0 = qs + wid*16 + (lane>>2);
    #pragma unroll
    for (int nf=0; nf<8; nf++){
        int n0 = nf*8 + ((lane&3)<<1);
        size_t idx0 = ((size_t)(b*SS + r0))*DD + h*64 + n0;
        *(uint32_t*)(g_ao + idx0) = packh(o[nf][0]*inv0, o[nf][1]*inv0);
        size_t idx1 = ((size_t)(b*SS + r0 + 8))*DD + h*64 + n0;
        *(uint32_t*)(g_ao + idx1) = packh(o[nf][2]*inv1, o[nf][3]*inv1);
    }
}

// ---------------------------------------------------------------------------
extern "C" void kernel_launch(void* const* d_in, const int* in_sizes, int n_in,
                              void* d_out, int out_size) {
    (void)in_sizes; (void)n_in; (void)out_size;
    const float* x    = (const float*)d_in[0];
    const float* Wqkv = (const float*)d_in[1];
    const float* bqkv = (const float*)d_in[2];
    const float* Wout = (const float*)d_in[3];
    const float* bout = (const float*)d_in[4];
    float* out = (float*)d_out;

    cudaFuncSetAttribute(gemm_mma<0>, cudaFuncAttributeMaxDynamicSharedMemorySize, GSMEM);
    cudaFuncSetAttribute(gemm_mma<1>, cudaFuncAttributeMaxDynamicSharedMemorySize, GSMEM);
    cudaFuncSetAttribute(attn_mma,    cudaFuncAttributeMaxDynamicSharedMemorySize, ASMEM);

    // 0) convert operands to fp16
    conv_h<0><<<(MTOT*DD/4 + 255)/256, 256>>>(x,    MTOT*DD/4);
    conv_h<1><<<(DD*NQKV/4 + 255)/256, 256>>>(Wqkv, DD*NQKV/4);
    conv_h<2><<<(DD*DD/4  + 255)/256, 256>>>(Wout,  DD*DD/4);

    // 1) QKV projection -> q(pre-scaled)/k/v fp16
    gemm_mma<0><<<dim3(NQKV/128, MTOT/128), 128, GSMEM>>>(bqkv, nullptr);

    // 2) causal attention -> g_ao (fp16)
    attn_mma<<<dim3(SS/128, BHH), 256, ASMEM>>>();

    // 3) output projection -> out
    gemm_mma<1><<<dim3(DD/128, MTOT/128), 128, GSMEM>>>(bout, out);
}

// round 15
// speedup vs baseline: 1.0588x; 1.0588x over previous
#include <cuda_runtime.h>
#include <cuda_fp16.h>
#include <cstdint>

#define BB 2
#define SS 2048
#define DD 1024
#define HH 16
#define HDD 64
#define BHH 32
#define MTOT 4096
#define NQKV 3072

// operands (__device__ globals: allocation-free rule), 16B aligned
__device__ __align__(16) __half g_xh[MTOT*DD];                     // x [m][k]
__device__ __align__(16) __half g_wqh[DD*NQKV];                    // W_qkv [k][n]
__device__ __align__(16) __half g_woh[DD*DD];                      // W_out  [k][n]
__device__ __align__(16) __half g_qh[BHH*SS*HDD];                  // q (pre-scaled by 0.125*log2e)
__device__ __align__(16) __half g_kh[BHH*SS*HDD];                  // k
__device__ __align__(16) __half g_vh[BHH*SS*HDD];                  // v
__device__ __align__(16) __half g_ao[MTOT*DD];                     // attn out [b*s][d]

// ---------------- helpers ----------------
__device__ __forceinline__ uint32_t smem_u32(const void* p){
    uint32_t a;
    asm("{ .reg .u64 t; cvta.to.shared.u64 t, %1; cvt.u32.u64 %0, t; }":"=r"(a):"l"(p));
    return a;
}
__device__ __forceinline__ void cp16(uint32_t d, const void* s){
    asm volatile("cp.async.cg.shared.global [%0], [%1], 16;"::"r"(d),"l"(s));
}
__device__ __forceinline__ void cp_commit(){ asm volatile("cp.async.commit_group;":::"memory"); }
template<int N> __device__ __forceinline__ void cp_wait(){
    asm volatile("cp.async.wait_group %0;"::"n"(N):"memory");
}
__device__ __forceinline__ void ldsm4(uint32_t* r, uint32_t a){
    asm volatile("ldmatrix.sync.aligned.m8n8.x4.shared.b16 {%0,%1,%2,%3}, [%4];"
        :"=r"(r[0]),"=r"(r[1]),"=r"(r[2]),"=r"(r[3]):"r"(a));
}
__device__ __forceinline__ void ldsm4t(uint32_t* r, uint32_t a){
    asm volatile("ldmatrix.sync.aligned.m8n8.x4.trans.shared.b16 {%0,%1,%2,%3}, [%4];"
        :"=r"(r[0]),"=r"(r[1]),"=r"(r[2]),"=r"(r[3]):"r"(a));
}
__device__ __forceinline__ void mma_h(float* c, const uint32_t* a, uint32_t b0, uint32_t b1){
    asm volatile("mma.sync.aligned.m16n8k16.row.col.f32.f16.f16.f32 "
        "{%0,%1,%2,%3}, {%4,%5,%6,%7}, {%8,%9}, {%0,%1,%2,%3};"
        :"+f"(c[0]),"+f"(c[1]),"+f"(c[2]),"+f"(c[3])
        :"r"(a[0]),"r"(a[1]),"r"(a[2]),"r"(a[3]),"r"(b0),"r"(b1));
}
__device__ __forceinline__ uint32_t packh(float x, float y){
    __half2 t = __floats2half2_rn(x, y);
    return *reinterpret_cast<uint32_t*>(&t);
}
__device__ __forceinline__ float ex2(float x){
    float y; asm("ex2.approx.f32 %0, %1;":"=f"(y):"f"(x)); return y;
}

#define QSCL 0.18033688f   // 0.125 * log2(e), folded into q

// ---------------- prep: fp32 -> fp16 ----------------
template<int SEL>
__global__ __launch_bounds__(256)
void conv_h(const float* __restrict__ src, int n4){
    __half* dst = (SEL==0)? g_xh : (SEL==1)? g_wqh : g_woh;
    int i = blockIdx.x*256 + threadIdx.x;
    if (i >= n4) return;
    float4 v = reinterpret_cast<const float4*>(src)[i];
    reinterpret_cast<uint32_t*>(dst)[i*2+0] = packh(v.x, v.y);
    reinterpret_cast<uint32_t*>(dst)[i*2+1] = packh(v.z, v.w);
}

// ---------------- fp16 GEMM: 128x128 CTA tile, 4 warps of 64x64, k-chunk 32 ----
// (R12 proven shape.)
// A tile: 128 rows x 32 fp16 (64B data, 80B stride)   -> 10240 B
// B tile:  32 k    x 128 fp16 (256B data, 272B stride) -> 8704 B
#define GSTAGE 18944
#define GSMEM  (3*GSTAGE)

template<int MODE>
__global__ __launch_bounds__(128, 2)
void gemm_mma(const float* __restrict__ bias, float* __restrict__ Cout){
    extern __shared__ char smem[];
    const __half* __restrict__ Ah = (MODE==0)? g_xh  : g_ao;
    const __half* __restrict__ Bh = (MODE==0)? g_wqh : g_woh;
    const int N = (MODE==0)? NQKV : DD;

    const int bm = blockIdx.y*128, bn = blockIdx.x*128;
    const int tid = threadIdx.x, lane = tid&31, wid = tid>>5;
    const int wm = wid>>1, wn = wid&1;   // warp tile 64(M) x 64(N)
    uint32_t sb = smem_u32(smem);

    float acc[4][8][4];
    #pragma unroll
    for (int a=0;a<4;a++)
        #pragma unroll
        for (int b=0;b<8;b++)
            #pragma unroll
            for (int c=0;c<4;c++) acc[a][b][c]=0.f;

    auto load_stage = [&](int t, int s){
        uint32_t as  = sb + s*GSTAGE;
        uint32_t bs2 = as + 10240;
        int k0 = t*32;
        // A: 512 x 16B
        #pragma unroll
        for (int i=0;i<4;i++){
            int id = i*128 + tid;
            int row = id>>2, seg = id&3;
            cp16(as + row*80 + seg*16, Ah + (size_t)(bm+row)*DD + k0 + seg*8);
        }
        // B: 512 x 16B
        #pragma unroll
        for (int i=0;i<4;i++){
            int id = i*128 + tid;
            int row = id>>4, seg = id&15;
            cp16(bs2 + row*272 + seg*16, Bh + (size_t)(k0+row)*N + bn + seg*8);
        }
        cp_commit();
    };

    load_stage(0,0);
    load_stage(1,1);
    int sl = 0, sl2 = 2;
    for (int t=0; t<32; t++){
        if (t<31) cp_wait<1>(); else cp_wait<0>();
        __syncthreads();
        if (t+2 < 32) load_stage(t+2, sl2);

        uint32_t as  = sb + sl*GSTAGE;
        uint32_t bs2 = as + 10240;
        #pragma unroll
        for (int k16=0;k16<2;k16++){
            uint32_t ah[4][4];
            #pragma unroll
            for (int mf=0;mf<4;mf++){
                uint32_t ad = as + (uint32_t)(wm*64+mf*16+(lane&15))*80
                            + k16*32 + ((lane>>4)<<4);
                ldsm4(ah[mf], ad);
            }
            uint32_t bhf[8][2];
            #pragma unroll
            for (int g=0;g<4;g++){
                uint32_t kk = (uint32_t)(k16*16 + (lane&15));
                uint32_t bd = bs2 + kk*272
                            + ((uint32_t)(wn*64 + g*16 + ((lane>>4)<<3))<<1);
                uint32_t t4[4];
                ldsm4t(t4, bd);
                bhf[g*2][0]=t4[0]; bhf[g*2][1]=t4[1];
                bhf[g*2+1][0]=t4[2]; bhf[g*2+1][1]=t4[3];
            }
            #pragma unroll
            for (int mf=0;mf<4;mf++)
                #pragma unroll
                for (int nf=0;nf<8;nf++)
                    mma_h(acc[mf][nf], ah[mf], bhf[nf][0], bhf[nf][1]);
        }
        sl  = (sl ==2)? 0 : sl+1;
        sl2 = (sl2==2)? 0 : sl2+1;
    }

    // epilogue
    #pragma unroll
    for (int mf=0;mf<4;mf++){
        #pragma unroll
        for (int nf=0;nf<8;nf++){
            int n0 = bn + wn*64 + nf*8 + ((lane&3)<<1);
            float b0v = bias[n0], b1v = bias[n0+1];
            #pragma unroll
            for (int hf2=0; hf2<2; hf2++){
                int m = bm + wm*64 + mf*16 + (lane>>2) + hf2*8;
                float v0 = acc[mf][nf][hf2*2+0] + b0v;
                float v1 = acc[mf][nf][hf2*2+1] + b1v;
                if (MODE==0){
                    int b = m>>11, s = m&(SS-1);
                    int h = n0/192, r = n0 - h*192;
                    size_t base = ((size_t)(b*HH+h)*SS + s)*HDD;
                    if (r < 64)       *(uint32_t*)(g_qh+base+r)     = packh(v0*QSCL,v1*QSCL);
                    else if (r < 128) *(uint32_t*)(g_kh+base+r-64)  = packh(v0,v1);
                    else              *(uint32_t*)(g_vh+base+r-128) = packh(v0,v1);
                } else {
                    float2 ov; ov.x = v0; ov.y = v1;
                    *(float2*)(Cout + (size_t)m*DD + n0) = ov;
                }
            }
        }
    }
}

// ---------------- flash attention, single fp16 operands ----------------
// CTA: 128 q-rows, 8 warps (warp = 16 rows x 64 cols). k-tiles 64, K/V dbl-buffered.
// Q pre-scaled by QSCL, so S-MMA output is already in log2 domain.
#define QTILE 18432
#define KTILE 9216
#define ASMEM (QTILE + 4*KTILE)   // 55296

__global__ __launch_bounds__(256, 2)
void attn_mma(){
    extern __shared__ char smem[];
    const int bh = blockIdx.y;
    const int qt = (int)gridDim.x - 1 - (int)blockIdx.x;   // big tiles first
    const int qs = qt*128;
    const int tid = threadIdx.x, lane = tid&31, wid = tid>>5;
    uint32_t sb = smem_u32(smem);
    const uint32_t Qs = sb;
    const uint32_t Kb[2] = {sb + QTILE, sb + QTILE + KTILE};
    const uint32_t Vb[2] = {sb + QTILE + 2*KTILE, sb + QTILE + 3*KTILE};
    const size_t hb = (size_t)bh*SS*HDD;
    const __half *qh = g_qh+hb, *kh = g_kh+hb, *vh = g_vh+hb;

    // Q tile: 1024 x 16B
    #pragma unroll
    for (int i=0;i<4;i++){
        int id = i*256+tid, row = id>>3, seg = id&7;
        cp16(Qs + row*144 + seg*16, qh + (size_t)(qs+row)*HDD + seg*8);
    }
    cp_commit();

    auto load_kv = [&](int jt, int b){
        int ks = jt*64;
        #pragma unroll
        for (int i=0;i<2;i++){
            int id = i*256+tid, row = id>>3, seg = id&7;
            cp16(Kb[b] + row*144 + seg*16, kh + (size_t)(ks+row)*HDD + seg*8);
        }
        #pragma unroll
        for (int i=0;i<2;i++){
            int id = i*256+tid, row = id>>3, seg = id&7;
            cp16(Vb[b] + row*144 + seg*16, vh + (size_t)(ks+row)*HDD + seg*8);
        }
        cp_commit();
    };
    load_kv(0, 0);

    float o[8][4];
    #pragma unroll
    for (int a=0;a<8;a++)
        #pragma unroll
        for (int b=0;b<4;b++) o[a][b]=0.f;
    float m0 = -1e30f, m1 = -1e30f, l0 = 0.f, l1 = 0.f;  // l: per-thread partial
    const int rg0 = qs + wid*16 + (lane>>2);
    const int rg1 = rg0 + 8;
    const int njt = 2*qt + 2;

    auto tile_step = [&](int jt, bool dia){
        cp_wait<0>();
        __syncthreads();
        if (jt+1 < njt) load_kv(jt+1, (jt+1)&1);

        const int ks = jt*64;
        const uint32_t Kc = Kb[jt&1], Vc = Vb[jt&1];

        // S = Q K^T (already log2-scaled via Q)
        float s[8][4];
        #pragma unroll
        for (int a=0;a<8;a++)
            #pragma unroll
            for (int b=0;b<4;b++) s[a][b]=0.f;
        #pragma unroll
        for (int kc=0; kc<4; kc++){
            uint32_t qf[4];
            uint32_t qa = Qs + (uint32_t)(wid*16 + (lane&15))*144
                        + kc*32 + ((lane>>4)<<4);
            ldsm4(qf, qa);
            uint32_t kt[4][4];
            #pragma unroll
            for (int np=0; np<4; np++){
                uint32_t row = (uint32_t)(np*16 + ((lane>>4)<<3) + (lane&7));
                uint32_t ka = Kc + row*144 + kc*32 + (((lane>>3)&1)<<4);
                ldsm4(kt[np], ka);
            }
            #pragma unroll
            for (int np=0; np<4; np++){
                mma_h(s[np*2],   qf, kt[np][0], kt[np][1]);
                mma_h(s[np*2+1], qf, kt[np][2], kt[np][3]);
            }
        }
        if (dia){
            #pragma unroll
            for (int nf=0; nf<8; nf++){
                int c = ks + nf*8 + ((lane&3)<<1);
                if (c   > rg0) s[nf][0] = -1e30f;
                if (c+1 > rg0) s[nf][1] = -1e30f;
                if (c   > rg1) s[nf][2] = -1e30f;
                if (c+1 > rg1) s[nf][3] = -1e30f;
            }
        }
        // row maxima (quad reduction; needed for uniform alpha)
        float mx0 = -1e30f, mx1 = -1e30f;
        #pragma unroll
        for (int nf=0;nf<8;nf++){
            mx0 = fmaxf(mx0, fmaxf(s[nf][0], s[nf][1]));
            mx1 = fmaxf(mx1, fmaxf(s[nf][2], s[nf][3]));
        }
        mx0 = fmaxf(mx0, __shfl_xor_sync(0xffffffffu, mx0, 1));
        mx0 = fmaxf(mx0, __shfl_xor_sync(0xffffffffu, mx0, 2));
        mx1 = fmaxf(mx1, __shfl_xor_sync(0xffffffffu, mx1, 1));
        mx1 = fmaxf(mx1, __shfl_xor_sync(0xffffffffu, mx1, 2));
        float m0n = fmaxf(m0, mx0), m1n = fmaxf(m1, mx1);
        float a0 = ex2(m0 - m0n), a1 = ex2(m1 - m1n);
        m0 = m0n; m1 = m1n;

        // P = 2^(S - m); l kept as per-thread partial (alpha is quad-uniform)
        float sum0 = 0.f, sum1 = 0.f;
        uint32_t ph[4][4];
        #pragma unroll
        for (int kc=0; kc<4; kc++){
            #pragma unroll
            for (int half=0; half<2; half++){
                int nf = kc*2 + half;
                float p0 = ex2(s[nf][0]-m0n), p1 = ex2(s[nf][1]-m0n);
                float p2 = ex2(s[nf][2]-m1n), p3 = ex2(s[nf][3]-m1n);
                sum0 += p0+p1; sum1 += p2+p3;
                ph[kc][half*2+0] = packh(p0,p1);
                ph[kc][half*2+1] = packh(p2,p3);
            }
        }
        l0 = l0*a0 + sum0; l1 = l1*a1 + sum1;
        #pragma unroll
        for (int nf=0;nf<8;nf++){
            o[nf][0]*=a0; o[nf][1]*=a0; o[nf][2]*=a1; o[nf][3]*=a1;
        }

        // O += P @ V
        #pragma unroll
        for (int kc=0; kc<4; kc++){
            uint32_t vf[4][4];
            #pragma unroll
            for (int g=0; g<4; g++){
                uint32_t va = Vc + (uint32_t)(kc*16 + (lane&15))*144
                            + ((uint32_t)(g*16 + ((lane>>4)<<3))<<1);
                ldsm4t(vf[g], va);
            }
            #pragma unroll
            for (int g=0; g<4; g++){
                mma_h(o[g*2],   ph[kc], vf[g][0], vf[g][1]);
                mma_h(o[g*2+1], ph[kc], vf[g][2], vf[g][3]);
            }
        }
    };

    for (int jt=0; jt<njt-2; jt++) tile_step(jt, false);
    tile_step(njt-2, true);
    tile_step(njt-1, true);

    // epilogue: quad-reduce l, then o/l -> fp16 -> g_ao[b*s][h*64+d]
    l0 += __shfl_xor_sync(0xffffffffu, l0, 1);
    l0 += __shfl_xor_sync(0xffffffffu, l0, 2);
    l1 += __shfl_xor_sync(0xffffffffu, l1, 1);
    l1 += __shfl_xor_sync(0xffffffffu, l1, 2);
    const int b = bh >> 4, h = bh & 15;
    float inv0 = 1.0f/l0, inv1 = 1.0f/l1;
    int r0 = qs + wid*16 + (lane>>2);
    #pragma unroll
    for (int nf=0; nf<8; nf++){
        int n0 = nf*8 + ((lane&3)<<1);
        size_t idx0 = ((size_t)(b*SS + r0))*DD + h*64 + n0;
        *(uint32_t*)(g_ao + idx0) = packh(o[nf][0]*inv0, o[nf][1]*inv0);
        size_t idx1 = ((size_t)(b*SS + r0 + 8))*DD + h*64 + n0;
        *(uint32_t*)(g_ao + idx1) = packh(o[nf][2]*inv1, o[nf][3]*inv1);
    }
}

// ---------------------------------------------------------------------------
extern "C" void kernel_launch(void* const* d_in, const int* in_sizes, int n_in,
                              void* d_out, int out_size) {
    (void)in_sizes; (void)n_in; (void)out_size;
    const float* x    = (const float*)d_in[0];
    const float* Wqkv = (const float*)d_in[1];
    const float* bqkv = (const float*)d_in[2];
    const float* Wout = (const float*)d_in[3];
    const float* bout = (const float*)d_in[4];
    float* out = (float*)d_out;

    cudaFuncSetAttribute(gemm_mma<0>, cudaFuncAttributeMaxDynamicSharedMemorySize, GSMEM);
    cudaFuncSetAttribute(gemm_mma<1>, cudaFuncAttributeMaxDynamicSharedMemorySize, GSMEM);
    cudaFuncSetAttribute(attn_mma,    cudaFuncAttributeMaxDynamicSharedMemorySize, ASMEM);

    // 0) convert operands to fp16
    conv_h<0><<<(MTOT*DD/4 + 255)/256, 256>>>(x,    MTOT*DD/4);
    conv_h<1><<<(DD*NQKV/4 + 255)/256, 256>>>(Wqkv, DD*NQKV/4);
    conv_h<2><<<(DD*DD/4  + 255)/256, 256>>>(Wout,  DD*DD/4);

    // 1) QKV projection -> q(pre-scaled)/k/v fp16
    gemm_mma<0><<<dim3(NQKV/128, MTOT/128), 128, GSMEM>>>(bqkv, nullptr);

    // 2) causal attention -> g_ao (fp16)
    attn_mma<<<dim3(SS/128, BHH), 256, ASMEM>>>();

    // 3) output projection -> out
    gemm_mma<1><<<dim3(DD/128, MTOT/128), 128, GSMEM>>>(bout, out);
}

// round 16
// speedup vs baseline: 1.0600x; 1.0011x over previous
#include <cuda_runtime.h>
#include <cuda_fp16.h>
#include <cstdint>

#define BB 2
#define SS 2048
#define DD 1024
#define HH 16
#define HDD 64
#define BHH 32
#define MTOT 4096
#define NQKV 3072

// operands (__device__ globals: allocation-free rule), 16B aligned
__device__ __align__(16) __half g_xh[MTOT*DD];                     // x [m][k]
__device__ __align__(16) __half g_wqh[DD*NQKV];                    // W_qkv [k][n]
__device__ __align__(16) __half g_woh[DD*DD];                      // W_out  [k][n]
__device__ __align__(16) __half g_qh[BHH*SS*HDD];                  // q (pre-scaled by 0.125*log2e)
__device__ __align__(16) __half g_kh[BHH*SS*HDD];                  // k
__device__ __align__(16) __half g_vh[BHH*SS*HDD];                  // v
__device__ __align__(16) __half g_ao[MTOT*DD];                     // attn out [b*s][d]

// ---------------- helpers ----------------
__device__ __forceinline__ uint32_t smem_u32(const void* p){
    uint32_t a;
    asm("{ .reg .u64 t; cvta.to.shared.u64 t, %1; cvt.u32.u64 %0, t; }":"=r"(a):"l"(p));
    return a;
}
__device__ __forceinline__ void cp16(uint32_t d, const void* s){
    asm volatile("cp.async.cg.shared.global [%0], [%1], 16;"::"r"(d),"l"(s));
}
__device__ __forceinline__ void cp_commit(){ asm volatile("cp.async.commit_group;":::"memory"); }
template<int N> __device__ __forceinline__ void cp_wait(){
    asm volatile("cp.async.wait_group %0;"::"n"(N):"memory");
}
__device__ __forceinline__ void ldsm4(uint32_t* r, uint32_t a){
    asm volatile("ldmatrix.sync.aligned.m8n8.x4.shared.b16 {%0,%1,%2,%3}, [%4];"
        :"=r"(r[0]),"=r"(r[1]),"=r"(r[2]),"=r"(r[3]):"r"(a));
}
__device__ __forceinline__ void ldsm4t(uint32_t* r, uint32_t a){
    asm volatile("ldmatrix.sync.aligned.m8n8.x4.trans.shared.b16 {%0,%1,%2,%3}, [%4];"
        :"=r"(r[0]),"=r"(r[1]),"=r"(r[2]),"=r"(r[3]):"r"(a));
}
__device__ __forceinline__ void mma_h(float* c, const uint32_t* a, uint32_t b0, uint32_t b1){
    asm volatile("mma.sync.aligned.m16n8k16.row.col.f32.f16.f16.f32 "
        "{%0,%1,%2,%3}, {%4,%5,%6,%7}, {%8,%9}, {%0,%1,%2,%3};"
        :"+f"(c[0]),"+f"(c[1]),"+f"(c[2]),"+f"(c[3])
        :"r"(a[0]),"r"(a[1]),"r"(a[2]),"r"(a[3]),"r"(b0),"r"(b1));
}
__device__ __forceinline__ uint32_t packh(float x, float y){
    __half2 t = __floats2half2_rn(x, y);
    return *reinterpret_cast<uint32_t*>(&t);
}
__device__ __forceinline__ float ex2(float x){
    float y; asm("ex2.approx.f32 %0, %1;":"=f"(y):"f"(x)); return y;
}

#define QSCL 0.18033688f   // 0.125 * log2(e), folded into q

// ---------------- prep: fp32 -> fp16, all three operands in one launch --------
#define N4_X   (MTOT*DD/4)
#define N4_WQ  (DD*NQKV/4)
#define N4_WO  (DD*DD/4)
#define N4_ALL (N4_X + N4_WQ + N4_WO)

__global__ __launch_bounds__(256)
void conv_all(const float* __restrict__ x, const float* __restrict__ wq,
              const float* __restrict__ wo){
    int i = blockIdx.x*256 + threadIdx.x;
    const float* src; __half* dst; int j;
    if (i < N4_X)            { src = x;  dst = g_xh;  j = i; }
    else if (i < N4_X+N4_WQ) { src = wq; dst = g_wqh; j = i - N4_X; }
    else if (i < N4_ALL)     { src = wo; dst = g_woh; j = i - N4_X - N4_WQ; }
    else return;
    float4 v = reinterpret_cast<const float4*>(src)[j];
    reinterpret_cast<uint32_t*>(dst)[j*2+0] = packh(v.x, v.y);
    reinterpret_cast<uint32_t*>(dst)[j*2+1] = packh(v.z, v.w);
}

// ---------------- fp16 GEMM: 128x128 CTA tile, 4 warps of 64x64, k-chunk 32 ----
// A tile: 128 rows x 32 fp16 (64B data, 80B stride)   -> 10240 B
// B tile:  32 k    x 128 fp16 (256B data, 272B stride) -> 8704 B
#define GSTAGE 18944
#define GSMEM  (3*GSTAGE)

template<int MODE>
__global__ __launch_bounds__(128, 2)
void gemm_mma(const float* __restrict__ bias, float* __restrict__ Cout){
    extern __shared__ char smem[];
    const __half* __restrict__ Ah = (MODE==0)? g_xh  : g_ao;
    const __half* __restrict__ Bh = (MODE==0)? g_wqh : g_woh;
    const int N = (MODE==0)? NQKV : DD;

    const int bm = blockIdx.y*128, bn = blockIdx.x*128;
    const int tid = threadIdx.x, lane = tid&31, wid = tid>>5;
    const int wm = wid>>1, wn = wid&1;   // warp tile 64(M) x 64(N)
    uint32_t sb = smem_u32(smem);

    float acc[4][8][4];
    #pragma unroll
    for (int a=0;a<4;a++)
        #pragma unroll
        for (int b=0;b<8;b++)
            #pragma unroll
            for (int c=0;c<4;c++) acc[a][b][c]=0.f;

    auto load_stage = [&](int t, int s){
        uint32_t as  = sb + s*GSTAGE;
        uint32_t bs2 = as + 10240;
        int k0 = t*32;
        #pragma unroll
        for (int i=0;i<4;i++){
            int id = i*128 + tid;
            int row = id>>2, seg = id&3;
            cp16(as + row*80 + seg*16, Ah + (size_t)(bm+row)*DD + k0 + seg*8);
        }
        #pragma unroll
        for (int i=0;i<4;i++){
            int id = i*128 + tid;
            int row = id>>4, seg = id&15;
            cp16(bs2 + row*272 + seg*16, Bh + (size_t)(k0+row)*N + bn + seg*8);
        }
        cp_commit();
    };

    load_stage(0,0);
    load_stage(1,1);
    int sl = 0, sl2 = 2;
    for (int t=0; t<32; t++){
        if (t<31) cp_wait<1>(); else cp_wait<0>();
        __syncthreads();
        if (t+2 < 32) load_stage(t+2, sl2);

        uint32_t as  = sb + sl*GSTAGE;
        uint32_t bs2 = as + 10240;
        #pragma unroll
        for (int k16=0;k16<2;k16++){
            uint32_t ah[4][4];
            #pragma unroll
            for (int mf=0;mf<4;mf++){
                uint32_t ad = as + (uint32_t)(wm*64+mf*16+(lane&15))*80
                            + k16*32 + ((lane>>4)<<4);
                ldsm4(ah[mf], ad);
            }
            uint32_t bhf[8][2];
            #pragma unroll
            for (int g=0;g<4;g++){
                uint32_t kk = (uint32_t)(k16*16 + (lane&15));
                uint32_t bd = bs2 + kk*272
                            + ((uint32_t)(wn*64 + g*16 + ((lane>>4)<<3))<<1);
                uint32_t t4[4];
                ldsm4t(t4, bd);
                bhf[g*2][0]=t4[0]; bhf[g*2][1]=t4[1];
                bhf[g*2+1][0]=t4[2]; bhf[g*2+1][1]=t4[3];
            }
            #pragma unroll
            for (int mf=0;mf<4;mf++)
                #pragma unroll
                for (int nf=0;nf<8;nf++)
                    mma_h(acc[mf][nf], ah[mf], bhf[nf][0], bhf[nf][1]);
        }
        sl  = (sl ==2)? 0 : sl+1;
        sl2 = (sl2==2)? 0 : sl2+1;
    }

    // epilogue
    #pragma unroll
    for (int mf=0;mf<4;mf++){
        #pragma unroll
        for (int nf=0;nf<8;nf++){
            int n0 = bn + wn*64 + nf*8 + ((lane&3)<<1);
            float b0v = bias[n0], b1v = bias[n0+1];
            #pragma unroll
            for (int hf2=0; hf2<2; hf2++){
                int m = bm + wm*64 + mf*16 + (lane>>2) + hf2*8;
                float v0 = acc[mf][nf][hf2*2+0] + b0v;
                float v1 = acc[mf][nf][hf2*2+1] + b1v;
                if (MODE==0){
                    int b = m>>11, s = m&(SS-1);
                    int h = n0/192, r = n0 - h*192;
                    size_t base = ((size_t)(b*HH+h)*SS + s)*HDD;
                    if (r < 64)       *(uint32_t*)(g_qh+base+r)     = packh(v0*QSCL,v1*QSCL);
                    else if (r < 128) *(uint32_t*)(g_kh+base+r-64)  = packh(v0,v1);
                    else              *(uint32_t*)(g_vh+base+r-128) = packh(v0,v1);
                } else {
                    float2 ov; ov.x = v0; ov.y = v1;
                    *(float2*)(Cout + (size_t)m*DD + n0) = ov;
                }
            }
        }
    }
}

// ---------------- flash attention: 4 warps x 32 q-rows, single fp16 ----------
// CTA: 128 q-rows. k-tiles 64, K/V double-buffered. Q pre-scaled (log2 domain).
#define QTILE 18432
#define KTILE 9216
#define ASMEM (QTILE + 4*KTILE)   // 55296

__global__ __launch_bounds__(128, 2)
void attn_mma(){
    extern __shared__ char smem[];
    const int bh = blockIdx.y;
    const int qt = (int)gridDim.x - 1 - (int)blockIdx.x;   // big tiles first
    const int qs = qt*128;
    const int tid = threadIdx.x, lane = tid&31, wid = tid>>5;   // wid 0..3
    uint32_t sb = smem_u32(smem);
    const uint32_t Qs = sb;
    const uint32_t Kb[2] = {sb + QTILE, sb + QTILE + KTILE};
    const uint32_t Vb[2] = {sb + QTILE + 2*KTILE, sb + QTILE + 3*KTILE};
    const size_t hb = (size_t)bh*SS*HDD;
    const __half *qh = g_qh+hb, *kh = g_kh+hb, *vh = g_vh+hb;

    // Q tile: 1024 x 16B, 128 threads
    #pragma unroll
    for (int i=0;i<8;i++){
        int id = i*128+tid, row = id>>3, seg = id&7;
        cp16(Qs + row*144 + seg*16, qh + (size_t)(qs+row)*HDD + seg*8);
    }
    cp_commit();

    auto load_kv = [&](int jt, int b){
        int ks = jt*64;
        #pragma unroll
        for (int i=0;i<4;i++){
            int id = i*128+tid, row = id>>3, seg = id&7;
            cp16(Kb[b] + row*144 + seg*16, kh + (size_t)(ks+row)*HDD + seg*8);
        }
        #pragma unroll
        for (int i=0;i<4;i++){
            int id = i*128+tid, row = id>>3, seg = id&7;
            cp16(Vb[b] + row*144 + seg*16, vh + (size_t)(ks+row)*HDD + seg*8);
        }
        cp_commit();
    };
    load_kv(0, 0);

    float o[2][8][4];
    #pragma unroll
    for (int a=0;a<2;a++)
        #pragma unroll
        for (int b=0;b<8;b++)
            #pragma unroll
            for (int c=0;c<4;c++) o[a][b][c]=0.f;
    float mrun[2][2], lrun[2][2];
    #pragma unroll
    for (int a=0;a<2;a++){ mrun[a][0]=-1e30f; mrun[a][1]=-1e30f; lrun[a][0]=0.f; lrun[a][1]=0.f; }
    const int rbase = qs + wid*32 + (lane>>2);   // + mf*16 (+8)
    const int njt = 2*qt + 2;

    auto tile_step = [&](int jt, bool dia){
        cp_wait<0>();
        __syncthreads();
        if (jt+1 < njt) load_kv(jt+1, (jt+1)&1);

        const int ks = jt*64;
        const uint32_t Kc = Kb[jt&1], Vc = Vb[jt&1];

        // S = Q K^T : warp covers 32 rows x 64 cols, k-dim 64
        float s[2][8][4];
        #pragma unroll
        for (int a=0;a<2;a++)
            #pragma unroll
            for (int b=0;b<8;b++)
                #pragma unroll
                for (int c=0;c<4;c++) s[a][b][c]=0.f;
        #pragma unroll
        for (int kc=0; kc<4; kc++){
            uint32_t qf[2][4];
            #pragma unroll
            for (int mf=0;mf<2;mf++){
                uint32_t qa = Qs + (uint32_t)(wid*32 + mf*16 + (lane&15))*144
                            + kc*32 + ((lane>>4)<<4);
                ldsm4(qf[mf], qa);
            }
            uint32_t kt[4][4];
            #pragma unroll
            for (int np=0; np<4; np++){
                uint32_t row = (uint32_t)(np*16 + ((lane>>4)<<3) + (lane&7));
                uint32_t ka = Kc + row*144 + kc*32 + (((lane>>3)&1)<<4);
                ldsm4(kt[np], ka);
            }
            #pragma unroll
            for (int mf=0;mf<2;mf++)
                #pragma unroll
                for (int np=0; np<4; np++){
                    mma_h(s[mf][np*2],   qf[mf], kt[np][0], kt[np][1]);
                    mma_h(s[mf][np*2+1], qf[mf], kt[np][2], kt[np][3]);
                }
        }
        if (dia){
            #pragma unroll
            for (int mf=0;mf<2;mf++){
                int r0 = rbase + mf*16, r1 = r0 + 8;
                #pragma unroll
                for (int nf=0; nf<8; nf++){
                    int c = ks + nf*8 + ((lane&3)<<1);
                    if (c   > r0) s[mf][nf][0] = -1e30f;
                    if (c+1 > r0) s[mf][nf][1] = -1e30f;
                    if (c   > r1) s[mf][nf][2] = -1e30f;
                    if (c+1 > r1) s[mf][nf][3] = -1e30f;
                }
            }
        }
        // softmax per mf
        uint32_t ph[2][4][4];
        #pragma unroll
        for (int mf=0;mf<2;mf++){
            float mx0 = -1e30f, mx1 = -1e30f;
            #pragma unroll
            for (int nf=0;nf<8;nf++){
                mx0 = fmaxf(mx0, fmaxf(s[mf][nf][0], s[mf][nf][1]));
                mx1 = fmaxf(mx1, fmaxf(s[mf][nf][2], s[mf][nf][3]));
            }
            mx0 = fmaxf(mx0, __shfl_xor_sync(0xffffffffu, mx0, 1));
            mx0 = fmaxf(mx0, __shfl_xor_sync(0xffffffffu, mx0, 2));
            mx1 = fmaxf(mx1, __shfl_xor_sync(0xffffffffu, mx1, 1));
            mx1 = fmaxf(mx1, __shfl_xor_sync(0xffffffffu, mx1, 2));
            float m0n = fmaxf(mrun[mf][0], mx0), m1n = fmaxf(mrun[mf][1], mx1);
            float a0 = ex2(mrun[mf][0] - m0n), a1 = ex2(mrun[mf][1] - m1n);
            mrun[mf][0] = m0n; mrun[mf][1] = m1n;

            float sum0 = 0.f, sum1 = 0.f;
            #pragma unroll
            for (int kc=0; kc<4; kc++){
                #pragma unroll
                for (int half=0; half<2; half++){
                    int nf = kc*2 + half;
                    float p0 = ex2(s[mf][nf][0]-m0n), p1 = ex2(s[mf][nf][1]-m0n);
                    float p2 = ex2(s[mf][nf][2]-m1n), p3 = ex2(s[mf][nf][3]-m1n);
                    sum0 += p0+p1; sum1 += p2+p3;
                    ph[mf][kc][half*2+0] = packh(p0,p1);
                    ph[mf][kc][half*2+1] = packh(p2,p3);
                }
            }
            lrun[mf][0] = lrun[mf][0]*a0 + sum0;
            lrun[mf][1] = lrun[mf][1]*a1 + sum1;
            #pragma unroll
            for (int nf=0;nf<8;nf++){
                o[mf][nf][0]*=a0; o[mf][nf][1]*=a0; o[mf][nf][2]*=a1; o[mf][nf][3]*=a1;
            }
        }

        // O += P @ V
        #pragma unroll
        for (int kc=0; kc<4; kc++){
            uint32_t vf[4][4];
            #pragma unroll
            for (int g=0; g<4; g++){
                uint32_t va = Vc + (uint32_t)(kc*16 + (lane&15))*144
                            + ((uint32_t)(g*16 + ((lane>>4)<<3))<<1);
                ldsm4t(vf[g], va);
            }
            #pragma unroll
            for (int mf=0;mf<2;mf++)
                #pragma unroll
                for (int g=0; g<4; g++){
                    mma_h(o[mf][g*2],   ph[mf][kc], vf[g][0], vf[g][1]);
                    mma_h(o[mf][g*2+1], ph[mf][kc], vf[g][2], vf[g][3]);
                }
        }
    };

    for (int jt=0; jt<njt-2; jt++) tile_step(jt, false);
    tile_step(njt-2, true);
    tile_step(njt-1, true);

    // epilogue: quad-reduce l, o/l -> fp16 -> g_ao[b*s][h*64+d]
    const int b = bh >> 4, h = bh & 15;
    #pragma unroll
    for (int mf=0;mf<2;mf++){
        float l0 = lrun[mf][0], l1 = lrun[mf][1];
        l0 += __shfl_xor_sync(0xffffffffu, l0, 1);
        l0 += __shfl_xor_sync(0xffffffffu, l0, 2);
        l1 += __shfl_xor_sync(0xffffffffu, l1, 1);
        l1 += __shfl_xor_sync(0xffffffffu, l1, 2);
        float inv0 = 1.0f/l0, inv1 = 1.0f/l1;
        int r0 = rbase + mf*16;
        #pragma unroll
        for (int nf=0; nf<8; nf++){
            int n0 = nf*8 + ((lane&3)<<1);
            size_t idx0 = ((size_t)(b*SS + r0))*DD + h*64 + n0;
            *(uint32_t*)(g_ao + idx0) = packh(o[mf][nf][0]*inv0, o[mf][nf][1]*inv0);
            size_t idx1 = ((size_t)(b*SS + r0 + 8))*DD + h*64 + n0;
            *(uint32_t*)(g_ao + idx1) = packh(o[mf][nf][2]*inv1, o[mf][nf][3]*inv1);
        }
    }
}

// ---------------------------------------------------------------------------
extern "C" void kernel_launch(void* const* d_in, const int* in_sizes, int n_in,
                              void* d_out, int out_size) {
    (void)in_sizes; (void)n_in; (void)out_size;
    const float* x    = (const float*)d_in[0];
    const float* Wqkv = (const float*)d_in[1];
    const float* bqkv = (const float*)d_in[2];
    const float* Wout = (const float*)d_in[3];
    const float* bout = (const float*)d_in[4];
    float* out = (float*)d_out;

    cudaFuncSetAttribute(gemm_mma<0>, cudaFuncAttributeMaxDynamicSharedMemorySize, GSMEM);
    cudaFuncSetAttribute(gemm_mma<1>, cudaFuncAttributeMaxDynamicSharedMemorySize, GSMEM);
    cudaFuncSetAttribute(attn_mma,    cudaFuncAttributeMaxDynamicSharedMemorySize, ASMEM);

    // 0) convert all operands to fp16 (single launch)
    conv_all<<<(N4_ALL + 255)/256, 256>>>(x, Wqkv, Wout);

    // 1) QKV projection -> q(pre-scaled)/k/v fp16
    gemm_mma<0><<<dim3(NQKV/128, MTOT/128), 128, GSMEM>>>(bqkv, nullptr);

    // 2) causal attention -> g_ao (fp16)
    attn_mma<<<dim3(SS/128, BHH), 128, ASMEM>>>();

    // 3) output projection -> out
    gemm_mma<1><<<dim3(DD/128, MTOT/128), 128, GSMEM>>>(bout, out);
}

// round 17
// speedup vs baseline: 1.0777x; 1.0167x over previous
#include <cuda_runtime.h>
#include <cuda_fp16.h>
#include <cstdint>

#define BB 2
#define SS 2048
#define DD 1024
#define HH 16
#define HDD 64
#define BHH 32
#define MTOT 4096
#define NQKV 3072

// operands (__device__ globals: allocation-free rule), 16B aligned
__device__ __align__(16) __half g_xh[MTOT*DD];                     // x [m][k]
__device__ __align__(16) __half g_wqh[DD*NQKV];                    // W_qkv [k][n]
__device__ __align__(16) __half g_woh[DD*DD];                      // W_out  [k][n]
__device__ __align__(16) __half g_qh[BHH*SS*HDD];                  // q (pre-scaled by 0.125*log2e)
__device__ __align__(16) __half g_kh[BHH*SS*HDD];                  // k
__device__ __align__(16) __half g_vh[BHH*SS*HDD];                  // v
__device__ __align__(16) __half g_ao[MTOT*DD];                     // attn out [b*s][d]

// ---------------- helpers ----------------
__device__ __forceinline__ uint32_t smem_u32(const void* p){
    uint32_t a;
    asm("{ .reg .u64 t; cvta.to.shared.u64 t, %1; cvt.u32.u64 %0, t; }":"=r"(a):"l"(p));
    return a;
}
__device__ __forceinline__ void cp16(uint32_t d, const void* s){
    asm volatile("cp.async.cg.shared.global [%0], [%1], 16;"::"r"(d),"l"(s));
}
__device__ __forceinline__ void cp_commit(){ asm volatile("cp.async.commit_group;":::"memory"); }
template<int N> __device__ __forceinline__ void cp_wait(){
    asm volatile("cp.async.wait_group %0;"::"n"(N):"memory");
}
__device__ __forceinline__ void ldsm4(uint32_t* r, uint32_t a){
    asm volatile("ldmatrix.sync.aligned.m8n8.x4.shared.b16 {%0,%1,%2,%3}, [%4];"
        :"=r"(r[0]),"=r"(r[1]),"=r"(r[2]),"=r"(r[3]):"r"(a));
}
__device__ __forceinline__ void ldsm4t(uint32_t* r, uint32_t a){
    asm volatile("ldmatrix.sync.aligned.m8n8.x4.trans.shared.b16 {%0,%1,%2,%3}, [%4];"
        :"=r"(r[0]),"=r"(r[1]),"=r"(r[2]),"=r"(r[3]):"r"(a));
}
__device__ __forceinline__ void mma_h(float* c, const uint32_t* a, uint32_t b0, uint32_t b1){
    asm volatile("mma.sync.aligned.m16n8k16.row.col.f32.f16.f16.f32 "
        "{%0,%1,%2,%3}, {%4,%5,%6,%7}, {%8,%9}, {%0,%1,%2,%3};"
        :"+f"(c[0]),"+f"(c[1]),"+f"(c[2]),"+f"(c[3])
        :"r"(a[0]),"r"(a[1]),"r"(a[2]),"r"(a[3]),"r"(b0),"r"(b1));
}
__device__ __forceinline__ uint32_t packh(float x, float y){
    __half2 t = __floats2half2_rn(x, y);
    return *reinterpret_cast<uint32_t*>(&t);
}
__device__ __forceinline__ float ex2(float x){
    float y; asm("ex2.approx.f32 %0, %1;":"=f"(y):"f"(x)); return y;
}

#define QSCL 0.18033688f   // 0.125 * log2(e), folded into q

// ---------------- prep: fp32 -> fp16, all three operands in one launch --------
#define N4_X   (MTOT*DD/4)
#define N4_WQ  (DD*NQKV/4)
#define N4_WO  (DD*DD/4)
#define N4_ALL (N4_X + N4_WQ + N4_WO)

__global__ __launch_bounds__(256)
void conv_all(const float* __restrict__ x, const float* __restrict__ wq,
              const float* __restrict__ wo){
    int i = blockIdx.x*256 + threadIdx.x;
    const float* src; __half* dst; int j;
    if (i < N4_X)            { src = x;  dst = g_xh;  j = i; }
    else if (i < N4_X+N4_WQ) { src = wq; dst = g_wqh; j = i - N4_X; }
    else if (i < N4_ALL)     { src = wo; dst = g_woh; j = i - N4_X - N4_WQ; }
    else return;
    float4 v = reinterpret_cast<const float4*>(src)[j];
    reinterpret_cast<uint32_t*>(dst)[j*2+0] = packh(v.x, v.y);
    reinterpret_cast<uint32_t*>(dst)[j*2+1] = packh(v.z, v.w);
}

// ---------------- fp16 GEMM: 128x128 CTA tile, 4 warps of 64x64, k-chunk 32 ----
// A tile: 128 rows x 32 fp16 (64B data, 80B stride)   -> 10240 B
// B tile:  32 k    x 128 fp16 (256B data, 272B stride) -> 8704 B
#define GSTAGE 18944
#define GSMEM  (3*GSTAGE)

template<int MODE>
__global__ __launch_bounds__(128, 2)
void gemm_mma(const float* __restrict__ bias, float* __restrict__ Cout){
    extern __shared__ char smem[];
    const __half* __restrict__ Ah = (MODE==0)? g_xh  : g_ao;
    const __half* __restrict__ Bh = (MODE==0)? g_wqh : g_woh;
    const int N = (MODE==0)? NQKV : DD;

    const int bm = blockIdx.y*128, bn = blockIdx.x*128;
    const int tid = threadIdx.x, lane = tid&31, wid = tid>>5;
    const int wm = wid>>1, wn = wid&1;   // warp tile 64(M) x 64(N)
    uint32_t sb = smem_u32(smem);

    float acc[4][8][4];
    #pragma unroll
    for (int a=0;a<4;a++)
        #pragma unroll
        for (int b=0;b<8;b++)
            #pragma unroll
            for (int c=0;c<4;c++) acc[a][b][c]=0.f;

    auto load_stage = [&](int t, int s){
        uint32_t as  = sb + s*GSTAGE;
        uint32_t bs2 = as + 10240;
        int k0 = t*32;
        #pragma unroll
        for (int i=0;i<4;i++){
            int id = i*128 + tid;
            int row = id>>2, seg = id&3;
            cp16(as + row*80 + seg*16, Ah + (size_t)(bm+row)*DD + k0 + seg*8);
        }
        #pragma unroll
        for (int i=0;i<4;i++){
            int id = i*128 + tid;
            int row = id>>4, seg = id&15;
            cp16(bs2 + row*272 + seg*16, Bh + (size_t)(k0+row)*N + bn + seg*8);
        }
        cp_commit();
    };

    load_stage(0,0);
    load_stage(1,1);
    int sl = 0, sl2 = 2;
    for (int t=0; t<32; t++){
        if (t<31) cp_wait<1>(); else cp_wait<0>();
        __syncthreads();
        if (t+2 < 32) load_stage(t+2, sl2);

        uint32_t as  = sb + sl*GSTAGE;
        uint32_t bs2 = as + 10240;
        #pragma unroll
        for (int k16=0;k16<2;k16++){
            uint32_t ah[4][4];
            #pragma unroll
            for (int mf=0;mf<4;mf++){
                uint32_t ad = as + (uint32_t)(wm*64+mf*16+(lane&15))*80
                            + k16*32 + ((lane>>4)<<4);
                ldsm4(ah[mf], ad);
            }
            uint32_t bhf[8][2];
            #pragma unroll
            for (int g=0;g<4;g++){
                uint32_t kk = (uint32_t)(k16*16 + (lane&15));
                uint32_t bd = bs2 + kk*272
                            + ((uint32_t)(wn*64 + g*16 + ((lane>>4)<<3))<<1);
                uint32_t t4[4];
                ldsm4t(t4, bd);
                bhf[g*2][0]=t4[0]; bhf[g*2][1]=t4[1];
                bhf[g*2+1][0]=t4[2]; bhf[g*2+1][1]=t4[3];
            }
            #pragma unroll
            for (int mf=0;mf<4;mf++)
                #pragma unroll
                for (int nf=0;nf<8;nf++)
                    mma_h(acc[mf][nf], ah[mf], bhf[nf][0], bhf[nf][1]);
        }
        sl  = (sl ==2)? 0 : sl+1;
        sl2 = (sl2==2)? 0 : sl2+1;
    }

    // epilogue
    #pragma unroll
    for (int mf=0;mf<4;mf++){
        #pragma unroll
        for (int nf=0;nf<8;nf++){
            int n0 = bn + wn*64 + nf*8 + ((lane&3)<<1);
            float b0v = bias[n0], b1v = bias[n0+1];
            #pragma unroll
            for (int hf2=0; hf2<2; hf2++){
                int m = bm + wm*64 + mf*16 + (lane>>2) + hf2*8;
                float v0 = acc[mf][nf][hf2*2+0] + b0v;
                float v1 = acc[mf][nf][hf2*2+1] + b1v;
                if (MODE==0){
                    int b = m>>11, s = m&(SS-1);
                    int h = n0/192, r = n0 - h*192;
                    size_t base = ((size_t)(b*HH+h)*SS + s)*HDD;
                    if (r < 64)       *(uint32_t*)(g_qh+base+r)     = packh(v0*QSCL,v1*QSCL);
                    else if (r < 128) *(uint32_t*)(g_kh+base+r-64)  = packh(v0,v1);
                    else              *(uint32_t*)(g_vh+base+r-128) = packh(v0,v1);
                } else {
                    float2 ov; ov.x = v0; ov.y = v1;
                    *(float2*)(Cout + (size_t)m*DD + n0) = ov;
                }
            }
        }
    }
}

// ---------------- flash attention: 4 warps x 32 q-rows, exp/PV interleaved ----
#define QTILE 18432
#define KTILE 9216
#define ASMEM (QTILE + 4*KTILE)   // 55296

__global__ __launch_bounds__(128, 2)
void attn_mma(){
    extern __shared__ char smem[];
    const int bh = blockIdx.y;
    const int qt = (int)gridDim.x - 1 - (int)blockIdx.x;   // big tiles first
    const int qs = qt*128;
    const int tid = threadIdx.x, lane = tid&31, wid = tid>>5;   // wid 0..3
    uint32_t sb = smem_u32(smem);
    const uint32_t Qs = sb;
    const uint32_t Kb[2] = {sb + QTILE, sb + QTILE + KTILE};
    const uint32_t Vb[2] = {sb + QTILE + 2*KTILE, sb + QTILE + 3*KTILE};
    const size_t hb = (size_t)bh*SS*HDD;
    const __half *qh = g_qh+hb, *kh = g_kh+hb, *vh = g_vh+hb;

    // Q tile: 1024 x 16B, 128 threads
    #pragma unroll
    for (int i=0;i<8;i++){
        int id = i*128+tid, row = id>>3, seg = id&7;
        cp16(Qs + row*144 + seg*16, qh + (size_t)(qs+row)*HDD + seg*8);
    }
    cp_commit();

    auto load_kv = [&](int jt, int b){
        int ks = jt*64;
        #pragma unroll
        for (int i=0;i<4;i++){
            int id = i*128+tid, row = id>>3, seg = id&7;
            cp16(Kb[b] + row*144 + seg*16, kh + (size_t)(ks+row)*HDD + seg*8);
        }
        #pragma unroll
        for (int i=0;i<4;i++){
            int id = i*128+tid, row = id>>3, seg = id&7;
            cp16(Vb[b] + row*144 + seg*16, vh + (size_t)(ks+row)*HDD + seg*8);
        }
        cp_commit();
    };
    load_kv(0, 0);

    float o[2][8][4];
    #pragma unroll
    for (int a=0;a<2;a++)
        #pragma unroll
        for (int b=0;b<8;b++)
            #pragma unroll
            for (int c=0;c<4;c++) o[a][b][c]=0.f;
    float mrun[2][2], lrun[2][2];
    #pragma unroll
    for (int a=0;a<2;a++){ mrun[a][0]=-1e30f; mrun[a][1]=-1e30f; lrun[a][0]=0.f; lrun[a][1]=0.f; }
    const int rbase = qs + wid*32 + (lane>>2);   // + mf*16 (+8)
    const int njt = 2*qt + 2;

    auto tile_step = [&](int jt, bool dia){
        cp_wait<0>();
        __syncthreads();
        if (jt+1 < njt) load_kv(jt+1, (jt+1)&1);

        const int ks = jt*64;
        const uint32_t Kc = Kb[jt&1], Vc = Vb[jt&1];

        // S = Q K^T : warp covers 32 rows x 64 cols, k-dim 64
        float s[2][8][4];
        #pragma unroll
        for (int a=0;a<2;a++)
            #pragma unroll
            for (int b=0;b<8;b++)
                #pragma unroll
                for (int c=0;c<4;c++) s[a][b][c]=0.f;
        #pragma unroll
        for (int kc=0; kc<4; kc++){
            uint32_t qf[2][4];
            #pragma unroll
            for (int mf=0;mf<2;mf++){
                uint32_t qa = Qs + (uint32_t)(wid*32 + mf*16 + (lane&15))*144
                            + kc*32 + ((lane>>4)<<4);
                ldsm4(qf[mf], qa);
            }
            uint32_t kt[4][4];
            #pragma unroll
            for (int np=0; np<4; np++){
                uint32_t row = (uint32_t)(np*16 + ((lane>>4)<<3) + (lane&7));
                uint32_t ka = Kc + row*144 + kc*32 + (((lane>>3)&1)<<4);
                ldsm4(kt[np], ka);
            }
            #pragma unroll
            for (int mf=0;mf<2;mf++)
                #pragma unroll
                for (int np=0; np<4; np++){
                    mma_h(s[mf][np*2],   qf[mf], kt[np][0], kt[np][1]);
                    mma_h(s[mf][np*2+1], qf[mf], kt[np][2], kt[np][3]);
                }
        }
        if (dia){
            #pragma unroll
            for (int mf=0;mf<2;mf++){
                int r0 = rbase + mf*16, r1 = r0 + 8;
                #pragma unroll
                for (int nf=0; nf<8; nf++){
                    int c = ks + nf*8 + ((lane&3)<<1);
                    if (c   > r0) s[mf][nf][0] = -1e30f;
                    if (c+1 > r0) s[mf][nf][1] = -1e30f;
                    if (c   > r1) s[mf][nf][2] = -1e30f;
                    if (c+1 > r1) s[mf][nf][3] = -1e30f;
                }
            }
        }
        // row maxima + alpha; rescale o (per mf)
        float mn0[2], mn1[2], a0s[2], a1s[2];
        #pragma unroll
        for (int mf=0;mf<2;mf++){
            float mx0 = -1e30f, mx1 = -1e30f;
            #pragma unroll
            for (int nf=0;nf<8;nf++){
                mx0 = fmaxf(mx0, fmaxf(s[mf][nf][0], s[mf][nf][1]));
                mx1 = fmaxf(mx1, fmaxf(s[mf][nf][2], s[mf][nf][3]));
            }
            mx0 = fmaxf(mx0, __shfl_xor_sync(0xffffffffu, mx0, 1));
            mx0 = fmaxf(mx0, __shfl_xor_sync(0xffffffffu, mx0, 2));
            mx1 = fmaxf(mx1, __shfl_xor_sync(0xffffffffu, mx1, 1));
            mx1 = fmaxf(mx1, __shfl_xor_sync(0xffffffffu, mx1, 2));
            float m0n = fmaxf(mrun[mf][0], mx0), m1n = fmaxf(mrun[mf][1], mx1);
            a0s[mf] = ex2(mrun[mf][0] - m0n);
            a1s[mf] = ex2(mrun[mf][1] - m1n);
            mrun[mf][0] = m0n; mrun[mf][1] = m1n;
            mn0[mf] = m0n; mn1[mf] = m1n;
            #pragma unroll
            for (int nf=0;nf<8;nf++){
                o[mf][nf][0]*=a0s[mf]; o[mf][nf][1]*=a0s[mf];
                o[mf][nf][2]*=a1s[mf]; o[mf][nf][3]*=a1s[mf];
            }
        }

        // interleaved: per kc -> V frags, exp+pack (MUFU), PV MMAs (tensor)
        float sm0[2] = {0.f, 0.f}, sm1[2] = {0.f, 0.f};
        #pragma unroll
        for (int kc=0; kc<4; kc++){
            uint32_t vf[4][4];
            #pragma unroll
            for (int g=0; g<4; g++){
                uint32_t va = Vc + (uint32_t)(kc*16 + (lane&15))*144
                            + ((uint32_t)(g*16 + ((lane>>4)<<3))<<1);
                ldsm4t(vf[g], va);
            }
            uint32_t ph[2][4];
            #pragma unroll
            for (int mf=0;mf<2;mf++){
                #pragma unroll
                for (int half=0; half<2; half++){
                    int nf = kc*2 + half;
                    float p0 = ex2(s[mf][nf][0]-mn0[mf]), p1 = ex2(s[mf][nf][1]-mn0[mf]);
                    float p2 = ex2(s[mf][nf][2]-mn1[mf]), p3 = ex2(s[mf][nf][3]-mn1[mf]);
                    sm0[mf] += p0+p1; sm1[mf] += p2+p3;
                    ph[mf][half*2+0] = packh(p0,p1);
                    ph[mf][half*2+1] = packh(p2,p3);
                }
            }
            #pragma unroll
            for (int mf=0;mf<2;mf++)
                #pragma unroll
                for (int g=0; g<4; g++){
                    mma_h(o[mf][g*2],   ph[mf], vf[g][0], vf[g][1]);
                    mma_h(o[mf][g*2+1], ph[mf], vf[g][2], vf[g][3]);
                }
        }
        #pragma unroll
        for (int mf=0;mf<2;mf++){
            lrun[mf][0] = lrun[mf][0]*a0s[mf] + sm0[mf];
            lrun[mf][1] = lrun[mf][1]*a1s[mf] + sm1[mf];
        }
    };

    for (int jt=0; jt<njt-2; jt++) tile_step(jt, false);
    tile_step(njt-2, true);
    tile_step(njt-1, true);

    // epilogue: quad-reduce l, o/l -> fp16 -> g_ao[b*s][h*64+d]
    const int b = bh >> 4, h = bh & 15;
    #pragma unroll
    for (int mf=0;mf<2;mf++){
        float l0 = lrun[mf][0], l1 = lrun[mf][1];
        l0 += __shfl_xor_sync(0xffffffffu, l0, 1);
        l0 += __shfl_xor_sync(0xffffffffu, l0, 2);
        l1 += __shfl_xor_sync(0xffffffffu, l1, 1);
        l1 += __shfl_xor_sync(0xffffffffu, l1, 2);
        float inv0 = 1.0f/l0, inv1 = 1.0f/l1;
        int r0 = rbase + mf*16;
        #pragma unroll
        for (int nf=0; nf<8; nf++){
            int n0 = nf*8 + ((lane&3)<<1);
            size_t idx0 = ((size_t)(b*SS + r0))*DD + h*64 + n0;
            *(uint32_t*)(g_ao + idx0) = packh(o[mf][nf][0]*inv0, o[mf][nf][1]*inv0);
            size_t idx1 = ((size_t)(b*SS + r0 + 8))*DD + h*64 + n0;
            *(uint32_t*)(g_ao + idx1) = packh(o[mf][nf][2]*inv1, o[mf][nf][3]*inv1);
        }
    }
}

// ---------------------------------------------------------------------------
extern "C" void kernel_launch(void* const* d_in, const int* in_sizes, int n_in,
                              void* d_out, int out_size) {
    (void)in_sizes; (void)n_in; (void)out_size;
    const float* x    = (const float*)d_in[0];
    const float* Wqkv = (const float*)d_in[1];
    const float* bqkv = (const float*)d_in[2];
    const float* Wout = (const float*)d_in[3];
    const float* bout = (const float*)d_in[4];
    float* out = (float*)d_out;

    cudaFuncSetAttribute(gemm_mma<0>, cudaFuncAttributeMaxDynamicSharedMemorySize, GSMEM);
    cudaFuncSetAttribute(gemm_mma<1>, cudaFuncAttributeMaxDynamicSharedMemorySize, GSMEM);
    cudaFuncSetAttribute(attn_mma,    cudaFuncAttributeMaxDynamicSharedMemorySize, ASMEM);

    // 0) convert all operands to fp16 (single launch)
    conv_all<<<(N4_ALL + 255)/256, 256>>>(x, Wqkv, Wout);

    // 1) QKV projection -> q(pre-scaled)/k/v fp16
    gemm_mma<0><<<dim3(NQKV/128, MTOT/128), 128, GSMEM>>>(bqkv, nullptr);

    // 2) causal attention -> g_ao (fp16)
    attn_mma<<<dim3(SS/128, BHH), 128, ASMEM>>>();

    // 3) output projection -> out
    gemm_mma<1><<<dim3(DD/128, MTOT/128), 128, GSMEM>>>(bout, out);
}